// round 2
// baseline (speedup 1.0000x reference)
#include <cuda_runtime.h>
#include <cuda_bf16.h>
#include <math.h>

#define N_TOK   8192
#define D_DIM   4096
#define N_EXP   64
#define TOP_K   2
#define CAP     160                          // ceil(1.25*8192/64)
#define NEC     (N_TOK * N_EXP * CAP)        // 83,886,080
#define FLAT    (N_TOK * TOP_K)              // 16384

typedef unsigned long long ull;

// ---------------- device scratch (no allocations allowed) ----------------
__device__ float g_gate_t[D_DIM * N_EXP];                    // gate^T [k][e]
__device__ __align__(16) unsigned char g_top_idx8[FLAT];     // expert ids
__device__ float g_top_w[FLAT];
__device__ int   g_slot[FLAT];
__device__ float g_psum[N_EXP];
__device__ int   g_cnt[N_EXP];

#define FMA2(d, a, b) asm("fma.rn.f32x2 %0, %1, %2, %0;" : "+l"(d) : "l"(a), "l"(b))
#define PACK2(d, s)   asm("mov.b64 %0, {%1, %1};" : "=l"(d) : "f"(s))
#define UNPACK2(lo, hi, s) asm("mov.b64 {%0, %1}, %2;" : "=f"(lo), "=f"(hi) : "l"(s))

// ---------------- gate transpose + psum zero ------------------------------
__global__ void k_transpose_gate(const float* __restrict__ gate_w) {
    int idx = blockIdx.x * blockDim.x + threadIdx.x;   // covers D*E
    int k = idx >> 6;
    int e = idx & 63;
    g_gate_t[idx] = gate_w[(size_t)e * D_DIM + k];
    if (blockIdx.x == 0 && threadIdx.x < N_EXP) g_psum[threadIdx.x] = 0.0f;
}

// ---------------- fused GEMM(f32x2) + softmax + top2 + zero-fill ----------
// 128 blocks x 256 threads; block covers 64 tokens x 64 experts; K-tile 64.
// Each block also zeroes 5.24MB of mask/combine output, interleaved with the
// FMA mainloop so DRAM writes overlap compute.
__global__ void __launch_bounds__(256)
k_gemm_topk(const float* __restrict__ x, float* __restrict__ probs_out,
            float* __restrict__ out_zero_base /* mask+comb, 2*NEC floats */) {
    __shared__ float xs[64][68];        // x tile [token][k], padded
    __shared__ float gs[64][64];        // gate tile [k][expert]
    __shared__ float smax[64], sinv[64];
    float (*lg)[65] = (float(*)[65])&xs[0][0];   // logits overlay on xs

    const int tid = threadIdx.x;
    const int tx = tid & 7;            // expert octet (8 experts)
    const int ty = tid >> 3;           // token pair (2 tokens)
    const int n0 = blockIdx.x * 64;

    // zero-fill region for this block: 327,680 float4 over 64 tile iters
    float4* zb = (float4*)out_zero_base + (size_t)blockIdx.x * 327680 + tid;
    const float4 z4 = make_float4(0.f, 0.f, 0.f, 0.f);

    ull acc0[4], acc1[4];
#pragma unroll
    for (int j = 0; j < 4; j++) { acc0[j] = 0ull; acc1[j] = 0ull; }

    for (int kc = 0; kc < D_DIM; kc += 64) {
        // load x tile: 64 tok x 64 k = 1024 float4
#pragma unroll
        for (int l = 0; l < 4; l++) {
            int idx = tid + l * 256;
            int t = idx >> 4, q = idx & 15;
            *(float4*)&xs[t][q * 4] =
                *(const float4*)&x[(size_t)(n0 + t) * D_DIM + kc + q * 4];
        }
        // load gate tile: 64 k x 64 e = 1024 float4
#pragma unroll
        for (int l = 0; l < 4; l++) {
            int idx = tid + l * 256;
            int kk = idx >> 4, q = idx & 15;
            *(float4*)&gs[kk][q * 4] =
                *(const float4*)&g_gate_t[(size_t)(kc + kk) * N_EXP + q * 4];
        }
        __syncthreads();

        // interleaved zero-fill stores (independent, hide under FMAs)
        {
            float4* z = zb + (kc >> 6) * 5120;
#pragma unroll
            for (int j = 0; j < 20; j++) z[j * 256] = z4;
        }

#pragma unroll 8
        for (int kk = 0; kk < 64; kk++) {
            float a0 = xs[2 * ty][kk];
            float a1 = xs[2 * ty + 1][kk];
            ull pa0, pa1;
            PACK2(pa0, a0);
            PACK2(pa1, a1);
            ulonglong2 gA = *(const ulonglong2*)&gs[kk][tx * 8];
            ulonglong2 gB = *(const ulonglong2*)&gs[kk][tx * 8 + 4];
            FMA2(acc0[0], pa0, gA.x); FMA2(acc0[1], pa0, gA.y);
            FMA2(acc0[2], pa0, gB.x); FMA2(acc0[3], pa0, gB.y);
            FMA2(acc1[0], pa1, gA.x); FMA2(acc1[1], pa1, gA.y);
            FMA2(acc1[2], pa1, gB.x); FMA2(acc1[3], pa1, gB.y);
        }
        __syncthreads();
    }

    // stage logits into shared (overlay on xs; safe after last sync)
#pragma unroll
    for (int j = 0; j < 4; j++) {
        float lo, hi;
        UNPACK2(lo, hi, acc0[j]);
        lg[2 * ty][tx * 8 + 2 * j] = lo;
        lg[2 * ty][tx * 8 + 2 * j + 1] = hi;
        UNPACK2(lo, hi, acc1[j]);
        lg[2 * ty + 1][tx * 8 + 2 * j] = lo;
        lg[2 * ty + 1][tx * 8 + 2 * j + 1] = hi;
    }
    __syncthreads();

    // per-token softmax stats + exact top-2 on fp32 logits
    if (tid < 64) {
        const int t = tid;
        float m = -INFINITY;
#pragma unroll
        for (int e = 0; e < N_EXP; e++) m = fmaxf(m, lg[t][e]);
        float s = 0.0f;
#pragma unroll
        for (int e = 0; e < N_EXP; e++) s += expf(lg[t][e] - m);
        float inv = 1.0f / s;
        smax[t] = m;
        sinv[t] = inv;

        float v1 = -INFINITY, v2 = -INFINITY;
        int i1 = 0, i2 = 0;
#pragma unroll
        for (int e = 0; e < N_EXP; e++) {
            float v = lg[t][e];
            if (v > v1) { v2 = v1; i2 = i1; v1 = v; i1 = e; }
            else if (v > v2) { v2 = v; i2 = e; }
        }
        float p1 = expf(v1 - m) * inv;
        float p2 = expf(v2 - m) * inv;
        float r = 1.0f / (p1 + p2);
        int n = n0 + t;
        *(uchar2*)&g_top_idx8[2 * n] = make_uchar2((unsigned char)i1,
                                                   (unsigned char)i2);
        *(float2*)&g_top_w[2 * n] = make_float2(p1 * r, p2 * r);
    }
    __syncthreads();

    // probs: each thread handles 1 token x 16 experts; also write p back
    // into lg for the column-sum below.
    {
        int t = tid >> 2;
        int e0 = (tid & 3) * 16;
        float m = smax[t], inv = sinv[t];
        float buf[16];
#pragma unroll
        for (int i = 0; i < 16; i++) {
            float p = expf(lg[t][e0 + i] - m) * inv;
            buf[i] = p;
        }
        float4* dst = (float4*)&probs_out[(size_t)(n0 + t) * N_EXP + e0];
#pragma unroll
        for (int q = 0; q < 4; q++)
            dst[q] = make_float4(buf[4 * q], buf[4 * q + 1],
                                 buf[4 * q + 2], buf[4 * q + 3]);
#pragma unroll
        for (int i = 0; i < 16; i++) lg[t][e0 + i] = buf[i];
    }
    __syncthreads();

    // per-expert prob column sums -> global accumulate
    if (tid < 64) {
        const int e = tid;
        float s = 0.0f;
#pragma unroll
        for (int t = 0; t < 64; t++) s += lg[t][e];
        atomicAdd(&g_psum[e], s);
    }
}

// ---------------- per-expert exclusive scan (register-resident) -----------
// 64 blocks (one per expert) x 256 threads; 64 byte-entries per thread.
__global__ void __launch_bounds__(256)
k_scan(void) {
    __shared__ int warp_sums[8];
    const int e = blockIdx.x;
    const int tid = threadIdx.x;
    const int lane = tid & 31;
    const int wid = tid >> 5;

    uint4 wv[4];
#pragma unroll
    for (int i = 0; i < 4; i++)
        wv[i] = ((const uint4*)g_top_idx8)[tid * 4 + i];
    unsigned w[16];
#pragma unroll
    for (int i = 0; i < 4; i++) {
        w[4 * i + 0] = wv[i].x; w[4 * i + 1] = wv[i].y;
        w[4 * i + 2] = wv[i].z; w[4 * i + 3] = wv[i].w;
    }

    const unsigned eb = (unsigned)e * 0x01010101u;
    int local = 0;
#pragma unroll
    for (int i = 0; i < 16; i++) local += __popc(__vcmpeq4(w[i], eb));
    local >>= 3;

    // warp inclusive scan
    int incl = local;
#pragma unroll
    for (int off = 1; off < 32; off <<= 1) {
        int v = __shfl_up_sync(0xffffffffu, incl, off);
        if (lane >= off) incl += v;
    }
    if (lane == 31) warp_sums[wid] = incl;
    __syncthreads();
    int base = 0;
#pragma unroll
    for (int j = 0; j < 8; j++) base += (j < wid) ? warp_sums[j] : 0;

    int c = base + incl - local;   // exclusive prefix for this thread
#pragma unroll
    for (int i = 0; i < 16; i++) {
        unsigned word = w[i];
#pragma unroll
        for (int b = 0; b < 4; b++) {
            if (((word >> (8 * b)) & 0xffu) == (unsigned)e)
                g_slot[tid * 64 + i * 4 + b] = c++;
        }
    }
    if (tid == 255) g_cnt[e] = base + incl;
}

// ---------------- scatter nonzeros + loss ---------------------------------
__global__ void __launch_bounds__(256)
k_scatter_loss(float* __restrict__ out_mask, float* __restrict__ out_comb,
               float* __restrict__ out_loss) {
    int i = blockIdx.x * 256 + threadIdx.x;   // 0..FLAT-1
    int e = g_top_idx8[i];
    int s = g_slot[i];
    if (s < CAP) {
        size_t off = (size_t)(i >> 1) * (N_EXP * CAP) + (size_t)e * CAP + s;
        out_mask[off] = 1.0f;
        out_comb[off] = g_top_w[i];
    }
    if (blockIdx.x == 0 && threadIdx.x < 64) {
        __shared__ float sh[64];
        int e2 = threadIdx.x;
        float f = (float)g_cnt[e2] / (float)FLAT;
        float p = g_psum[e2] / (float)N_TOK;
        sh[e2] = f * p;
        __syncthreads();
        for (int off = 32; off > 0; off >>= 1) {
            if (e2 < off) sh[e2] += sh[e2 + off];
            __syncthreads();
        }
        if (e2 == 0) out_loss[0] = 0.01f * (float)N_EXP * sh[0];
    }
}

// ---------------- launch ---------------------------------------------------
extern "C" void kernel_launch(void* const* d_in, const int* in_sizes, int n_in,
                              void* d_out, int out_size) {
    const float* x      = (const float*)d_in[0];
    const float* gate_w = (const float*)d_in[1];
    float* out = (float*)d_out;

    float* out_mask  = out;                                   // N*E*C
    float* out_comb  = out + (size_t)NEC;                     // N*E*C
    float* out_probs = out + (size_t)2 * NEC;                 // N*E
    float* out_loss  = out + (size_t)2 * NEC + (size_t)N_TOK * N_EXP;

    k_transpose_gate<<<(D_DIM * N_EXP) / 256, 256>>>(gate_w);
    k_gemm_topk<<<N_TOK / 64, 256>>>(x, out_probs, out);      // zeroes mask+comb
    k_scan<<<N_EXP, 256>>>();
    k_scatter_loss<<<FLAT / 256, 256>>>(out_mask, out_comb, out_loss);
}

// round 5
// speedup vs baseline: 1.0873x; 1.0873x over previous
#include <cuda_runtime.h>
#include <cuda_bf16.h>
#include <math.h>

#define N_TOK   8192
#define D_DIM   4096
#define N_EXP   64
#define TOP_K   2
#define CAP     160                          // ceil(1.25*8192/64)
#define NEC     (N_TOK * N_EXP * CAP)        // 83,886,080
#define FLAT    (N_TOK * TOP_K)              // 16384

#define GEMM_BLOCKS 128
#define GRID_TOTAL  296                      // 128 GEMM + 168 zero workers
#define ZCHUNK      4096                     // float4 per steal (64KB)
#define ZTOTAL4     (2u * NEC / 4)           // 41,943,040 float4 to zero
#define NCHUNKS     (ZTOTAL4 / ZCHUNK)       // 10240 exactly

typedef unsigned long long ull;

// ---------------- device scratch (ALL 16B-aligned explicitly) -------------
__device__ __align__(16) float g_gate_t[D_DIM * N_EXP];      // gate^T [k][e]
__device__ __align__(16) unsigned char g_top_idx8[FLAT];     // expert ids
__device__ __align__(16) float g_top_w[FLAT];
__device__ __align__(16) float g_psum[N_EXP];
__device__ __align__(16) unsigned g_zctr;                    // zero ticket

#define FMA2(d, a, b) asm("fma.rn.f32x2 %0, %1, %2, %0;" : "+l"(d) : "l"(a), "l"(b))
#define PACK2(d, s)   asm("mov.b64 %0, {%1, %1};" : "=l"(d) : "f"(s))
#define UNPACK2(lo, hi, s) asm("mov.b64 {%0, %1}, %2;" : "=f"(lo), "=f"(hi) : "l"(s))

// ---------------- gate transpose + scratch init ---------------------------
__global__ void k_transpose_gate(const float* __restrict__ gate_w,
                                 float* __restrict__ out_loss) {
    int idx = blockIdx.x * blockDim.x + threadIdx.x;   // covers D*E
    int k = idx >> 6;
    int e = idx & 63;
    g_gate_t[idx] = gate_w[(size_t)e * D_DIM + k];
    if (blockIdx.x == 0) {
        if (threadIdx.x < N_EXP) g_psum[threadIdx.x] = 0.0f;
        if (threadIdx.x == 64) g_zctr = 0u;
        if (threadIdx.x == 65) out_loss[0] = 0.0f;
    }
}

// ---------------- zero-fill steal loop (block-cooperative) ----------------
__device__ __forceinline__ void zero_steal(float4* __restrict__ zbase,
                                           unsigned* sc) {
    const float4 z4 = make_float4(0.f, 0.f, 0.f, 0.f);
    const int tid = threadIdx.x;
    for (;;) {
        if (tid == 0) *sc = atomicAdd(&g_zctr, 1u);
        __syncthreads();
        unsigned c = *sc;
        __syncthreads();
        if (c >= NCHUNKS) return;
        float4* z = zbase + (size_t)c * ZCHUNK + tid;
#pragma unroll
        for (int j = 0; j < ZCHUNK / 256; j++) z[j * 256] = z4;
    }
}

// ---------------- mega kernel: GEMM+topk blocks + zero blocks -------------
__global__ void __launch_bounds__(256)
k_mega(const float* __restrict__ x, float* __restrict__ probs_out,
       float* __restrict__ out_zero_base /* mask+comb = 2*NEC floats */) {
    __shared__ __align__(16) float xs[64][68];   // x tile / logits overlay
    __shared__ __align__(16) float gs[64][64];   // gate tile [k][expert]
    __shared__ float smax[64], sinv[64];
    __shared__ unsigned sc;
    float (*lg)[68] = xs;                        // stride 68: rows 16B-aligned

    if (blockIdx.x >= GEMM_BLOCKS) {    // -------- zero-fill worker --------
        zero_steal((float4*)out_zero_base, &sc);
        return;
    }

    // ------------------------------- GEMM -------------------------------
    const int tid = threadIdx.x;
    const int tx = tid & 7;            // expert octet (8 experts)
    const int ty = tid >> 3;           // token pair (2 tokens)
    const int n0 = blockIdx.x * 64;

    ull acc0[4], acc1[4];
#pragma unroll
    for (int j = 0; j < 4; j++) { acc0[j] = 0ull; acc1[j] = 0ull; }

    for (int kc = 0; kc < D_DIM; kc += 64) {
#pragma unroll
        for (int l = 0; l < 4; l++) {
            int idx = tid + l * 256;
            int t = idx >> 4, q = idx & 15;
            *(float4*)&xs[t][q * 4] =
                *(const float4*)&x[(size_t)(n0 + t) * D_DIM + kc + q * 4];
        }
#pragma unroll
        for (int l = 0; l < 4; l++) {
            int idx = tid + l * 256;
            int kk = idx >> 4, q = idx & 15;
            *(float4*)&gs[kk][q * 4] =
                *(const float4*)&g_gate_t[(size_t)(kc + kk) * N_EXP + q * 4];
        }
        __syncthreads();

#pragma unroll 8
        for (int kk = 0; kk < 64; kk++) {
            float a0 = xs[2 * ty][kk];
            float a1 = xs[2 * ty + 1][kk];
            ull pa0, pa1;
            PACK2(pa0, a0);
            PACK2(pa1, a1);
            ulonglong2 gA = *(const ulonglong2*)&gs[kk][tx * 8];
            ulonglong2 gB = *(const ulonglong2*)&gs[kk][tx * 8 + 4];
            FMA2(acc0[0], pa0, gA.x); FMA2(acc0[1], pa0, gA.y);
            FMA2(acc0[2], pa0, gB.x); FMA2(acc0[3], pa0, gB.y);
            FMA2(acc1[0], pa1, gA.x); FMA2(acc1[1], pa1, gA.y);
            FMA2(acc1[2], pa1, gB.x); FMA2(acc1[3], pa1, gB.y);
        }
        __syncthreads();
    }

    // stage logits into shared (stride-68 overlay on xs)
#pragma unroll
    for (int j = 0; j < 4; j++) {
        float lo, hi;
        UNPACK2(lo, hi, acc0[j]);
        lg[2 * ty][tx * 8 + 2 * j]     = lo;
        lg[2 * ty][tx * 8 + 2 * j + 1] = hi;
        UNPACK2(lo, hi, acc1[j]);
        lg[2 * ty + 1][tx * 8 + 2 * j]     = lo;
        lg[2 * ty + 1][tx * 8 + 2 * j + 1] = hi;
    }
    __syncthreads();

    // per-token softmax stats + exact top-2 on fp32 logits
    if (tid < 64) {
        const int t = tid;
        float m = -INFINITY;
#pragma unroll
        for (int e = 0; e < N_EXP; e++) m = fmaxf(m, lg[t][e]);
        float s = 0.0f;
#pragma unroll
        for (int e = 0; e < N_EXP; e++) s += expf(lg[t][e] - m);
        float inv = 1.0f / s;
        smax[t] = m;
        sinv[t] = inv;

        float v1 = -INFINITY, v2 = -INFINITY;
        int i1 = 0, i2 = 0;
#pragma unroll
        for (int e = 0; e < N_EXP; e++) {
            float v = lg[t][e];
            if (v > v1) { v2 = v1; i2 = i1; v1 = v; i1 = e; }
            else if (v > v2) { v2 = v; i2 = e; }
        }
        float p1 = expf(v1 - m) * inv;
        float p2 = expf(v2 - m) * inv;
        float r = 1.0f / (p1 + p2);
        int n = n0 + t;
        g_top_idx8[2 * n]     = (unsigned char)i1;   // scalar byte stores
        g_top_idx8[2 * n + 1] = (unsigned char)i2;
        g_top_w[2 * n]     = p1 * r;                 // scalar float stores
        g_top_w[2 * n + 1] = p2 * r;
    }
    __syncthreads();

    // probs: 1 token x 16 experts per thread; keep p in lg for column sums
    {
        int t = tid >> 2;
        int e0 = (tid & 3) * 16;                     // 16B-aligned group
        float m = smax[t], inv = sinv[t];
        float buf[16];
#pragma unroll
        for (int i = 0; i < 16; i++) buf[i] = expf(lg[t][e0 + i] - m) * inv;
        float4* dst = (float4*)&probs_out[(size_t)(n0 + t) * N_EXP + e0];
#pragma unroll
        for (int q = 0; q < 4; q++)
            dst[q] = make_float4(buf[4 * q], buf[4 * q + 1],
                                 buf[4 * q + 2], buf[4 * q + 3]);
#pragma unroll
        for (int i = 0; i < 16; i++) lg[t][e0 + i] = buf[i];
    }
    __syncthreads();

    if (tid < 64) {
        const int e = tid;
        float s = 0.0f;
#pragma unroll
        for (int t = 0; t < 64; t++) s += lg[t][e];
        atomicAdd(&g_psum[e], s);
    }
    __syncthreads();

    // done with GEMM -> help zero-fill (self-balancing tail)
    zero_steal((float4*)out_zero_base, &sc);
}

// ---------------- scan + scatter + loss (one block per expert) ------------
__global__ void __launch_bounds__(256)
k_scan_scatter_loss(float* __restrict__ out_mask,
                    float* __restrict__ out_comb,
                    float* __restrict__ out_loss) {
    __shared__ int warp_sums[8];
    const int e = blockIdx.x;
    const int tid = threadIdx.x;
    const int lane = tid & 31;
    const int wid = tid >> 5;

    uint4 wv[4];
#pragma unroll
    for (int i = 0; i < 4; i++)
        wv[i] = ((const uint4*)g_top_idx8)[tid * 4 + i];
    unsigned w[16];
#pragma unroll
    for (int i = 0; i < 4; i++) {
        w[4 * i + 0] = wv[i].x; w[4 * i + 1] = wv[i].y;
        w[4 * i + 2] = wv[i].z; w[4 * i + 3] = wv[i].w;
    }

    const unsigned eb = (unsigned)e * 0x01010101u;
    int local = 0;
#pragma unroll
    for (int i = 0; i < 16; i++) local += __popc(__vcmpeq4(w[i], eb));
    local >>= 3;

    int incl = local;
#pragma unroll
    for (int off = 1; off < 32; off <<= 1) {
        int v = __shfl_up_sync(0xffffffffu, incl, off);
        if (lane >= off) incl += v;
    }
    if (lane == 31) warp_sums[wid] = incl;
    __syncthreads();
    int base = 0;
#pragma unroll
    for (int j = 0; j < 8; j++) base += (j < wid) ? warp_sums[j] : 0;

    int c = base + incl - local;   // exclusive prefix for this thread
#pragma unroll
    for (int i = 0; i < 16; i++) {
        unsigned word = w[i];
#pragma unroll
        for (int b = 0; b < 4; b++) {
            if (((word >> (8 * b)) & 0xffu) == (unsigned)e) {
                if (c < CAP) {
                    int fi = tid * 64 + i * 4 + b;
                    size_t off = (size_t)(fi >> 1) * (N_EXP * CAP)
                               + (size_t)e * CAP + c;
                    out_mask[off] = 1.0f;
                    out_comb[off] = g_top_w[fi];
                }
                c++;
            }
        }
    }
    if (tid == 255) {
        int total = base + incl;                       // count for expert e
        float f = (float)total / (float)FLAT;
        float p = g_psum[e] / (float)N_TOK;
        atomicAdd(out_loss, 0.01f * (float)N_EXP * f * p);
    }
}

// ---------------- launch ---------------------------------------------------
extern "C" void kernel_launch(void* const* d_in, const int* in_sizes, int n_in,
                              void* d_out, int out_size) {
    const float* x      = (const float*)d_in[0];
    const float* gate_w = (const float*)d_in[1];
    float* out = (float*)d_out;

    float* out_mask  = out;                                   // N*E*C
    float* out_comb  = out + (size_t)NEC;                     // N*E*C
    float* out_probs = out + (size_t)2 * NEC;                 // N*E
    float* out_loss  = out + (size_t)2 * NEC + (size_t)N_TOK * N_EXP;

    k_transpose_gate<<<(D_DIM * N_EXP) / 256, 256>>>(gate_w, out_loss);
    k_mega<<<GRID_TOTAL, 256>>>(x, out_probs, out);
    k_scan_scatter_loss<<<N_EXP, 256>>>(out_mask, out_comb, out_loss);
}

// round 6
// speedup vs baseline: 1.1831x; 1.0881x over previous
#include <cuda_runtime.h>
#include <cuda_bf16.h>
#include <math.h>

#define N_TOK   8192
#define D_DIM   4096
#define N_EXP   64
#define TOP_K   2
#define CAP     160                          // ceil(1.25*8192/64)
#define NEC     (N_TOK * N_EXP * CAP)        // 83,886,080
#define FLAT    (N_TOK * TOP_K)              // 16384

#define GEMM_BLOCKS 128
#define GRID_TOTAL  148                      // 128 GEMM + 20 bulk-zero, 1 CTA/SM
#define OP_BYTES    16384                    // one cp.async.bulk store
#define CHUNK_BYTES 65536                    // one ticket = 4 bulk ops
#define NCHUNKS     (2u * NEC * 4u / CHUNK_BYTES)   // 10240

typedef unsigned long long ull;

// ---------------- device scratch (16B-aligned) ----------------------------
__device__ __align__(16) float g_gate_t[D_DIM * N_EXP];      // gate^T [k][e]
__device__ __align__(16) unsigned char g_top_idx8[FLAT];     // expert ids
__device__ __align__(16) float g_top_w[FLAT];
__device__ __align__(16) float g_psum[N_EXP];
__device__ __align__(16) unsigned g_zctr;                    // zero ticket

#define FMA2(d, a, b) asm("fma.rn.f32x2 %0, %1, %2, %0;" : "+l"(d) : "l"(a), "l"(b))
#define PACK2(d, s)   asm("mov.b64 %0, {%1, %1};" : "=l"(d) : "f"(s))
#define UNPACK2(lo, hi, s) asm("mov.b64 {%0, %1}, %2;" : "=f"(lo), "=f"(hi) : "l"(s))

__device__ __forceinline__ unsigned smem_u32(const void* p) {
    unsigned a;
    asm("{ .reg .u64 t; cvta.to.shared.u64 t, %1; cvt.u32.u64 %0, t; }"
        : "=r"(a) : "l"(p));
    return a;
}

// ---------------- gate transpose + scratch init ---------------------------
__global__ void k_transpose_gate(const float* __restrict__ gate_w,
                                 float* __restrict__ out_loss) {
    int idx = blockIdx.x * blockDim.x + threadIdx.x;   // covers D*E
    int k = idx >> 6;
    int e = idx & 63;
    g_gate_t[idx] = gate_w[(size_t)e * D_DIM + k];
    if (blockIdx.x == 0) {
        if (threadIdx.x < N_EXP) g_psum[threadIdx.x] = 0.0f;
        if (threadIdx.x == 64) g_zctr = 0u;
        if (threadIdx.x == 65) out_loss[0] = 0.0f;
    }
}

// ---------------- bulk-zero steal loop (warp 0 of a block) ----------------
__device__ __forceinline__ void bulk_zero_steal(char* __restrict__ dst_base,
                                                unsigned src_smem) {
    const int lane = threadIdx.x & 31;
    for (;;) {
        unsigned c;
        if (lane == 0) c = atomicAdd(&g_zctr, 1u);
        c = __shfl_sync(0xffffffffu, c, 0);
        if (c >= NCHUNKS) break;
        if (lane == 0) {
            char* dst = dst_base + (size_t)c * CHUNK_BYTES;
#pragma unroll
            for (int i = 0; i < CHUNK_BYTES / OP_BYTES; i++) {
                asm volatile(
                    "cp.async.bulk.global.shared::cta.bulk_group [%0], [%1], %2;"
                    :: "l"(dst + i * OP_BYTES), "r"(src_smem), "r"(OP_BYTES)
                    : "memory");
            }
            asm volatile("cp.async.bulk.commit_group;" ::: "memory");
            asm volatile("cp.async.bulk.wait_group.read 16;" ::: "memory");
        }
    }
    if (lane == 0)
        asm volatile("cp.async.bulk.wait_group 0;" ::: "memory");
}

// ---------------- mega kernel: GEMM blocks + bulk-zero blocks -------------
__global__ void __launch_bounds__(256)
k_mega(const float* __restrict__ x, float* __restrict__ probs_out,
       float* __restrict__ out_zero_base /* mask+comb = 2*NEC floats */) {
    __shared__ __align__(16) float xs[64][68];   // x tile / logits / zero src
    __shared__ __align__(16) float gs[64][64];   // gate tile [k][expert]
    __shared__ float smax[64], sinv[64];
    float (*lg)[68] = xs;                        // logits overlay, 16B rows

    const int tid = threadIdx.x;

    if (blockIdx.x >= GEMM_BLOCKS) {    // ---------- bulk-zero worker ------
        float4* z = (float4*)&xs[0][0];
#pragma unroll
        for (int j = 0; j < 4; j++)
            z[tid + j * 256] = make_float4(0.f, 0.f, 0.f, 0.f);
        __syncthreads();
        asm volatile("fence.proxy.async.shared::cta;" ::: "memory");
        if (tid < 32)
            bulk_zero_steal((char*)out_zero_base, smem_u32(&xs[0][0]));
        return;
    }

    // ------------------------------- GEMM -------------------------------
    const int tx = tid & 7;            // expert octet (8 experts)
    const int ty = tid >> 3;           // token pair (2 tokens)
    const int n0 = blockIdx.x * 64;

    ull acc0[4], acc1[4];
#pragma unroll
    for (int j = 0; j < 4; j++) { acc0[j] = 0ull; acc1[j] = 0ull; }

    // register double-buffer: prefetch tile 0
    float4 px[4], pg[4];
#pragma unroll
    for (int l = 0; l < 4; l++) {
        int idx = tid + l * 256;
        int t = idx >> 4, q = idx & 15;
        px[l] = *(const float4*)&x[(size_t)(n0 + t) * D_DIM + q * 4];
        pg[l] = *(const float4*)&g_gate_t[(size_t)t * N_EXP + q * 4];
    }

    for (int kc = 0; kc < D_DIM; kc += 64) {
#pragma unroll
        for (int l = 0; l < 4; l++) {
            int idx = tid + l * 256;
            int t = idx >> 4, q = idx & 15;
            *(float4*)&xs[t][q * 4] = px[l];
            *(float4*)&gs[t][q * 4] = pg[l];
        }
        __syncthreads();

        if (kc + 64 < D_DIM) {
#pragma unroll
            for (int l = 0; l < 4; l++) {
                int idx = tid + l * 256;
                int t = idx >> 4, q = idx & 15;
                px[l] = *(const float4*)
                    &x[(size_t)(n0 + t) * D_DIM + kc + 64 + q * 4];
                pg[l] = *(const float4*)
                    &g_gate_t[(size_t)(kc + 64 + t) * N_EXP + q * 4];
            }
        }

#pragma unroll 8
        for (int kk = 0; kk < 64; kk++) {
            float a0 = xs[2 * ty][kk];
            float a1 = xs[2 * ty + 1][kk];
            ull pa0, pa1;
            PACK2(pa0, a0);
            PACK2(pa1, a1);
            ulonglong2 gA = *(const ulonglong2*)&gs[kk][tx * 8];
            ulonglong2 gB = *(const ulonglong2*)&gs[kk][tx * 8 + 4];
            FMA2(acc0[0], pa0, gA.x); FMA2(acc0[1], pa0, gA.y);
            FMA2(acc0[2], pa0, gB.x); FMA2(acc0[3], pa0, gB.y);
            FMA2(acc1[0], pa1, gA.x); FMA2(acc1[1], pa1, gA.y);
            FMA2(acc1[2], pa1, gB.x); FMA2(acc1[3], pa1, gB.y);
        }
        __syncthreads();
    }

    // stage logits into shared (stride-68 overlay on xs)
#pragma unroll
    for (int j = 0; j < 4; j++) {
        float lo, hi;
        UNPACK2(lo, hi, acc0[j]);
        lg[2 * ty][tx * 8 + 2 * j]     = lo;
        lg[2 * ty][tx * 8 + 2 * j + 1] = hi;
        UNPACK2(lo, hi, acc1[j]);
        lg[2 * ty + 1][tx * 8 + 2 * j]     = lo;
        lg[2 * ty + 1][tx * 8 + 2 * j + 1] = hi;
    }
    __syncthreads();

    // per-token softmax stats + exact top-2 on fp32 logits
    if (tid < 64) {
        const int t = tid;
        float m = -INFINITY;
#pragma unroll
        for (int e = 0; e < N_EXP; e++) m = fmaxf(m, lg[t][e]);
        float s = 0.0f;
#pragma unroll
        for (int e = 0; e < N_EXP; e++) s += expf(lg[t][e] - m);
        float inv = 1.0f / s;
        smax[t] = m;
        sinv[t] = inv;

        float v1 = -INFINITY, v2 = -INFINITY;
        int i1 = 0, i2 = 0;
#pragma unroll
        for (int e = 0; e < N_EXP; e++) {
            float v = lg[t][e];
            if (v > v1) { v2 = v1; i2 = i1; v1 = v; i1 = e; }
            else if (v > v2) { v2 = v; i2 = e; }
        }
        float p1 = expf(v1 - m) * inv;
        float p2 = expf(v2 - m) * inv;
        float r = 1.0f / (p1 + p2);
        int n = n0 + t;
        g_top_idx8[2 * n]     = (unsigned char)i1;
        g_top_idx8[2 * n + 1] = (unsigned char)i2;
        g_top_w[2 * n]     = p1 * r;
        g_top_w[2 * n + 1] = p2 * r;
    }
    __syncthreads();

    // probs: 1 token x 16 experts per thread; keep p in lg for column sums
    {
        int t = tid >> 2;
        int e0 = (tid & 3) * 16;
        float m = smax[t], inv = sinv[t];
        float buf[16];
#pragma unroll
        for (int i = 0; i < 16; i++) buf[i] = expf(lg[t][e0 + i] - m) * inv;
        float4* dst = (float4*)&probs_out[(size_t)(n0 + t) * N_EXP + e0];
#pragma unroll
        for (int q = 0; q < 4; q++)
            dst[q] = make_float4(buf[4 * q], buf[4 * q + 1],
                                 buf[4 * q + 2], buf[4 * q + 3]);
#pragma unroll
        for (int i = 0; i < 16; i++) lg[t][e0 + i] = buf[i];
    }
    __syncthreads();

    if (tid < 64) {
        const int e = tid;
        float s = 0.0f;
#pragma unroll
        for (int t = 0; t < 64; t++) s += lg[t][e];
        atomicAdd(&g_psum[e], s);
    }
    __syncthreads();

    // re-zero xs as DMA source, then help with bulk zero-fill
    {
        float4* z = (float4*)&xs[0][0];
#pragma unroll
        for (int j = 0; j < 4; j++)
            z[tid + j * 256] = make_float4(0.f, 0.f, 0.f, 0.f);
        __syncthreads();
        asm volatile("fence.proxy.async.shared::cta;" ::: "memory");
        if (tid < 32)
            bulk_zero_steal((char*)out_zero_base, smem_u32(&xs[0][0]));
    }
}

// ---------------- scan + scatter + loss (one block per expert) ------------
__global__ void __launch_bounds__(256)
k_scan_scatter_loss(float* __restrict__ out_mask,
                    float* __restrict__ out_comb,
                    float* __restrict__ out_loss) {
    __shared__ int warp_sums[8];
    const int e = blockIdx.x;
    const int tid = threadIdx.x;
    const int lane = tid & 31;
    const int wid = tid >> 5;

    uint4 wv[4];
#pragma unroll
    for (int i = 0; i < 4; i++)
        wv[i] = ((const uint4*)g_top_idx8)[tid * 4 + i];
    unsigned w[16];
#pragma unroll
    for (int i = 0; i < 4; i++) {
        w[4 * i + 0] = wv[i].x; w[4 * i + 1] = wv[i].y;
        w[4 * i + 2] = wv[i].z; w[4 * i + 3] = wv[i].w;
    }

    const unsigned eb = (unsigned)e * 0x01010101u;
    int local = 0;
#pragma unroll
    for (int i = 0; i < 16; i++) local += __popc(__vcmpeq4(w[i], eb));
    local >>= 3;

    int incl = local;
#pragma unroll
    for (int off = 1; off < 32; off <<= 1) {
        int v = __shfl_up_sync(0xffffffffu, incl, off);
        if (lane >= off) incl += v;
    }
    if (lane == 31) warp_sums[wid] = incl;
    __syncthreads();
    int base = 0;
#pragma unroll
    for (int j = 0; j < 8; j++) base += (j < wid) ? warp_sums[j] : 0;

    int c = base + incl - local;   // exclusive prefix for this thread
#pragma unroll
    for (int i = 0; i < 16; i++) {
        unsigned word = w[i];
#pragma unroll
        for (int b = 0; b < 4; b++) {
            if (((word >> (8 * b)) & 0xffu) == (unsigned)e) {
                if (c < CAP) {
                    int fi = tid * 64 + i * 4 + b;
                    size_t off = (size_t)(fi >> 1) * (N_EXP * CAP)
                               + (size_t)e * CAP + c;
                    out_mask[off] = 1.0f;
                    out_comb[off] = g_top_w[fi];
                }
                c++;
            }
        }
    }
    if (tid == 255) {
        int total = base + incl;                       // count for expert e
        float f = (float)total / (float)FLAT;
        float p = g_psum[e] / (float)N_TOK;
        atomicAdd(out_loss, 0.01f * (float)N_EXP * f * p);
    }
}

// ---------------- launch ---------------------------------------------------
extern "C" void kernel_launch(void* const* d_in, const int* in_sizes, int n_in,
                              void* d_out, int out_size) {
    const float* x      = (const float*)d_in[0];
    const float* gate_w = (const float*)d_in[1];
    float* out = (float*)d_out;

    float* out_mask  = out;                                   // N*E*C
    float* out_comb  = out + (size_t)NEC;                     // N*E*C
    float* out_probs = out + (size_t)2 * NEC;                 // N*E
    float* out_loss  = out + (size_t)2 * NEC + (size_t)N_TOK * N_EXP;

    k_transpose_gate<<<(D_DIM * N_EXP) / 256, 256>>>(gate_w, out_loss);
    k_mega<<<GRID_TOTAL, 256>>>(x, out_probs, out);
    k_scan_scatter_loss<<<N_EXP, 256>>>(out_mask, out_comb, out_loss);
}

// round 7
// speedup vs baseline: 1.1834x; 1.0003x over previous
#include <cuda_runtime.h>
#include <cuda_bf16.h>
#include <math.h>

#define N_TOK   8192
#define D_DIM   4096
#define N_EXP   64
#define TOP_K   2
#define CAP     160                          // ceil(1.25*8192/64)
#define NEC     (N_TOK * N_EXP * CAP)        // 83,886,080
#define FLAT    (N_TOK * TOP_K)              // 16384

#define ZERO_BLOCKS 20
#define GRID_TOTAL  148                      // 20 zero + 128 GEMM, 1 CTA/SM
#define OP_BYTES    16384                    // one cp.async.bulk store
#define CHUNK_BYTES 65536                    // one ticket = 4 bulk ops
#define NCHUNKS     (2u * NEC * 4u / CHUNK_BYTES)   // 10240

// ---------------- device scratch (16B-aligned) ----------------------------
__device__ __align__(16) float g_gate_t[D_DIM * N_EXP];      // gate^T [k][e]
__device__ __align__(16) unsigned char g_top_idx8[FLAT];     // expert ids
__device__ __align__(16) float g_top_w[FLAT];
__device__ __align__(16) float g_psum[N_EXP];
__device__ __align__(16) unsigned g_zctr;                    // zero ticket

__device__ __forceinline__ unsigned smem_u32(const void* p) {
    unsigned a;
    asm("{ .reg .u64 t; cvta.to.shared.u64 t, %1; cvt.u32.u64 %0, t; }"
        : "=r"(a) : "l"(p));
    return a;
}

// ---------------- gate transpose + scratch init ---------------------------
__global__ void k_transpose_gate(const float* __restrict__ gate_w,
                                 float* __restrict__ out_loss) {
    int idx = blockIdx.x * blockDim.x + threadIdx.x;   // covers D*E
    int k = idx >> 6;
    int e = idx & 63;
    g_gate_t[idx] = gate_w[(size_t)e * D_DIM + k];
    if (blockIdx.x == 0) {
        if (threadIdx.x < N_EXP) g_psum[threadIdx.x] = 0.0f;
        if (threadIdx.x == 64) g_zctr = 0u;
        if (threadIdx.x == 65) out_loss[0] = 0.0f;
    }
}

// ---------------- bulk-zero steal loop (per-warp tickets) -----------------
// Every warp that enters steals 64KB tickets; lane 0 issues 4x16KB bulk
// stores from a pre-zeroed SMEM region via the async proxy (no LSU cost).
__device__ __forceinline__ void bulk_zero_steal(char* __restrict__ dst_base,
                                                unsigned src_smem) {
    const int lane = threadIdx.x & 31;
    for (;;) {
        unsigned c;
        if (lane == 0) c = atomicAdd(&g_zctr, 1u);
        c = __shfl_sync(0xffffffffu, c, 0);
        if (c >= NCHUNKS) break;
        if (lane == 0) {
            char* dst = dst_base + (size_t)c * CHUNK_BYTES;
#pragma unroll
            for (int i = 0; i < CHUNK_BYTES / OP_BYTES; i++) {
                asm volatile(
                    "cp.async.bulk.global.shared::cta.bulk_group [%0], [%1], %2;"
                    :: "l"(dst + i * OP_BYTES), "r"(src_smem), "r"(OP_BYTES)
                    : "memory");
            }
            asm volatile("cp.async.bulk.commit_group;" ::: "memory");
            // keep up to 8 groups (512KB) in flight per warp
            asm volatile("cp.async.bulk.wait_group.read 8;" ::: "memory");
        }
    }
    if (lane == 0)
        asm volatile("cp.async.bulk.wait_group 0;" ::: "memory");
}

// ---------------- mega kernel: zero blocks + GEMM blocks ------------------
__global__ void __launch_bounds__(256)
k_mega(const float* __restrict__ x, float* __restrict__ probs_out,
       float* __restrict__ out_zero_base /* mask+comb = 2*NEC floats */) {
    __shared__ __align__(16) float xs[64][68];   // x tile / logits / zero src
    __shared__ __align__(16) float gs[64][64];   // gate tile [k][expert]
    __shared__ float smax[64], sinv[64];
    float (*lg)[68] = xs;                        // logits overlay, 16B rows

    const int tid = threadIdx.x;

    if (blockIdx.x < ZERO_BLOCKS) {     // ---------- bulk-zero worker ------
        float4* z = (float4*)&xs[0][0];
#pragma unroll
        for (int j = 0; j < 4; j++)
            z[tid + j * 256] = make_float4(0.f, 0.f, 0.f, 0.f);
        __syncthreads();
        asm volatile("fence.proxy.async.shared::cta;" ::: "memory");
        bulk_zero_steal((char*)out_zero_base, smem_u32(&xs[0][0]));
        return;
    }

    // ------------------------------- GEMM -------------------------------
    const int tx = tid & 7;            // expert octet (8 experts)
    const int ty = tid >> 3;           // token pair (2 tokens)
    const int n0 = (blockIdx.x - ZERO_BLOCKS) * 64;

    float acc0[8], acc1[8];
#pragma unroll
    for (int j = 0; j < 8; j++) { acc0[j] = 0.0f; acc1[j] = 0.0f; }

    // register double-buffer: prefetch tile 0
    float4 px[4], pg[4];
#pragma unroll
    for (int l = 0; l < 4; l++) {
        int idx = tid + l * 256;
        int t = idx >> 4, q = idx & 15;
        px[l] = *(const float4*)&x[(size_t)(n0 + t) * D_DIM + q * 4];
        pg[l] = *(const float4*)&g_gate_t[(size_t)t * N_EXP + q * 4];
    }

    for (int kc = 0; kc < D_DIM; kc += 64) {
#pragma unroll
        for (int l = 0; l < 4; l++) {
            int idx = tid + l * 256;
            int t = idx >> 4, q = idx & 15;
            *(float4*)&xs[t][q * 4] = px[l];
            *(float4*)&gs[t][q * 4] = pg[l];
        }
        __syncthreads();

        if (kc + 64 < D_DIM) {
#pragma unroll
            for (int l = 0; l < 4; l++) {
                int idx = tid + l * 256;
                int t = idx >> 4, q = idx & 15;
                px[l] = *(const float4*)
                    &x[(size_t)(n0 + t) * D_DIM + kc + 64 + q * 4];
                pg[l] = *(const float4*)
                    &g_gate_t[(size_t)(kc + 64 + t) * N_EXP + q * 4];
            }
        }

#pragma unroll 8
        for (int kk = 0; kk < 64; kk++) {
            float a0 = xs[2 * ty][kk];
            float a1 = xs[2 * ty + 1][kk];
            float4 gA = *(const float4*)&gs[kk][tx * 8];
            float4 gB = *(const float4*)&gs[kk][tx * 8 + 4];
            acc0[0] += a0 * gA.x; acc0[1] += a0 * gA.y;
            acc0[2] += a0 * gA.z; acc0[3] += a0 * gA.w;
            acc0[4] += a0 * gB.x; acc0[5] += a0 * gB.y;
            acc0[6] += a0 * gB.z; acc0[7] += a0 * gB.w;
            acc1[0] += a1 * gA.x; acc1[1] += a1 * gA.y;
            acc1[2] += a1 * gA.z; acc1[3] += a1 * gA.w;
            acc1[4] += a1 * gB.x; acc1[5] += a1 * gB.y;
            acc1[6] += a1 * gB.z; acc1[7] += a1 * gB.w;
        }
        __syncthreads();
    }

    // stage logits into shared (stride-68 overlay on xs)
#pragma unroll
    for (int j = 0; j < 8; j++) {
        lg[2 * ty][tx * 8 + j]     = acc0[j];
        lg[2 * ty + 1][tx * 8 + j] = acc1[j];
    }
    __syncthreads();

    // per-token softmax stats + exact top-2 on fp32 logits
    if (tid < 64) {
        const int t = tid;
        float m = -INFINITY;
#pragma unroll
        for (int e = 0; e < N_EXP; e++) m = fmaxf(m, lg[t][e]);
        float s = 0.0f;
#pragma unroll
        for (int e = 0; e < N_EXP; e++) s += expf(lg[t][e] - m);
        float inv = 1.0f / s;
        smax[t] = m;
        sinv[t] = inv;

        float v1 = -INFINITY, v2 = -INFINITY;
        int i1 = 0, i2 = 0;
#pragma unroll
        for (int e = 0; e < N_EXP; e++) {
            float v = lg[t][e];
            if (v > v1) { v2 = v1; i2 = i1; v1 = v; i1 = e; }
            else if (v > v2) { v2 = v; i2 = e; }
        }
        float p1 = expf(v1 - m) * inv;
        float p2 = expf(v2 - m) * inv;
        float r = 1.0f / (p1 + p2);
        int n = n0 + t;
        g_top_idx8[2 * n]     = (unsigned char)i1;
        g_top_idx8[2 * n + 1] = (unsigned char)i2;
        g_top_w[2 * n]     = p1 * r;
        g_top_w[2 * n + 1] = p2 * r;
    }
    __syncthreads();

    // probs: 1 token x 16 experts per thread; keep p in lg for column sums
    {
        int t = tid >> 2;
        int e0 = (tid & 3) * 16;
        float m = smax[t], inv = sinv[t];
        float buf[16];
#pragma unroll
        for (int i = 0; i < 16; i++) buf[i] = expf(lg[t][e0 + i] - m) * inv;
        float4* dst = (float4*)&probs_out[(size_t)(n0 + t) * N_EXP + e0];
#pragma unroll
        for (int q = 0; q < 4; q++)
            dst[q] = make_float4(buf[4 * q], buf[4 * q + 1],
                                 buf[4 * q + 2], buf[4 * q + 3]);
#pragma unroll
        for (int i = 0; i < 16; i++) lg[t][e0 + i] = buf[i];
    }
    __syncthreads();

    if (tid < 64) {
        const int e = tid;
        float s = 0.0f;
#pragma unroll
        for (int t = 0; t < 64; t++) s += lg[t][e];
        atomicAdd(&g_psum[e], s);
    }
    __syncthreads();

    // re-zero xs as DMA source, then all warps help with bulk zero-fill
    {
        float4* z = (float4*)&xs[0][0];
#pragma unroll
        for (int j = 0; j < 4; j++)
            z[tid + j * 256] = make_float4(0.f, 0.f, 0.f, 0.f);
        __syncthreads();
        asm volatile("fence.proxy.async.shared::cta;" ::: "memory");
        bulk_zero_steal((char*)out_zero_base, smem_u32(&xs[0][0]));
    }
}

// ---------------- scan + scatter + loss (one block per expert) ------------
__global__ void __launch_bounds__(256)
k_scan_scatter_loss(float* __restrict__ out_mask,
                    float* __restrict__ out_comb,
                    float* __restrict__ out_loss) {
    __shared__ int warp_sums[8];
    const int e = blockIdx.x;
    const int tid = threadIdx.x;
    const int lane = tid & 31;
    const int wid = tid >> 5;

    uint4 wv[4];
#pragma unroll
    for (int i = 0; i < 4; i++)
        wv[i] = ((const uint4*)g_top_idx8)[tid * 4 + i];
    unsigned w[16];
#pragma unroll
    for (int i = 0; i < 4; i++) {
        w[4 * i + 0] = wv[i].x; w[4 * i + 1] = wv[i].y;
        w[4 * i + 2] = wv[i].z; w[4 * i + 3] = wv[i].w;
    }

    const unsigned eb = (unsigned)e * 0x01010101u;
    int local = 0;
#pragma unroll
    for (int i = 0; i < 16; i++) local += __popc(__vcmpeq4(w[i], eb));
    local >>= 3;

    int incl = local;
#pragma unroll
    for (int off = 1; off < 32; off <<= 1) {
        int v = __shfl_up_sync(0xffffffffu, incl, off);
        if (lane >= off) incl += v;
    }
    if (lane == 31) warp_sums[wid] = incl;
    __syncthreads();
    int base = 0;
#pragma unroll
    for (int j = 0; j < 8; j++) base += (j < wid) ? warp_sums[j] : 0;

    int c = base + incl - local;   // exclusive prefix for this thread
#pragma unroll
    for (int i = 0; i < 16; i++) {
        unsigned word = w[i];
#pragma unroll
        for (int b = 0; b < 4; b++) {
            if (((word >> (8 * b)) & 0xffu) == (unsigned)e) {
                if (c < CAP) {
                    int fi = tid * 64 + i * 4 + b;
                    size_t off = (size_t)(fi >> 1) * (N_EXP * CAP)
                               + (size_t)e * CAP + c;
                    out_mask[off] = 1.0f;
                    out_comb[off] = g_top_w[fi];
                }
                c++;
            }
        }
    }
    if (tid == 255) {
        int total = base + incl;                       // count for expert e
        float f = (float)total / (float)FLAT;
        float p = g_psum[e] / (float)N_TOK;
        atomicAdd(out_loss, 0.01f * (float)N_EXP * f * p);
    }
}

// ---------------- launch ---------------------------------------------------
extern "C" void kernel_launch(void* const* d_in, const int* in_sizes, int n_in,
                              void* d_out, int out_size) {
    const float* x      = (const float*)d_in[0];
    const float* gate_w = (const float*)d_in[1];
    float* out = (float*)d_out;

    float* out_mask  = out;                                   // N*E*C
    float* out_comb  = out + (size_t)NEC;                     // N*E*C
    float* out_probs = out + (size_t)2 * NEC;                 // N*E
    float* out_loss  = out + (size_t)2 * NEC + (size_t)N_TOK * N_EXP;

    k_transpose_gate<<<(D_DIM * N_EXP) / 256, 256>>>(gate_w, out_loss);
    k_mega<<<GRID_TOTAL, 256>>>(x, out_probs, out);
    k_scan_scatter_loss<<<N_EXP, 256>>>(out_mask, out_comb, out_loss);
}

// round 9
// speedup vs baseline: 1.4083x; 1.1900x over previous
#include <cuda_runtime.h>
#include <cuda_bf16.h>
#include <math.h>
#include <stdint.h>

#define N_TOK   8192
#define D_DIM   4096
#define N_EXP   64
#define CAP     160                          // ceil(1.25*8192/64)
#define NEC     (N_TOK * N_EXP * CAP)        // 83,886,080
#define FLAT    (N_TOK * 2)                  // 16384

#define TILE_K  64
#define NTILES  (D_DIM / TILE_K)             // 64
#define GEMM_GRID (N_TOK / 64)               // 128 blocks, 64 tokens each
#define LDS_S   68                           // smem row stride (floats)

// dynamic smem layout (u32 units)
#define XB_OFF  0                            // x big   [64][68]
#define XS_OFF  4352                         // x small
#define GB_OFF  8704                         // gate big
#define GS_OFF  13056                        // gate small
#define SMEM_U32 17408
#define SMEM_BYTES (SMEM_U32 * 4)            // 69,632

// ---------------- device scratch ------------------------------------------
__device__ __align__(16) float g_gate_t[D_DIM * N_EXP];      // gate^T [k][e]
__device__ __align__(16) unsigned char g_top_idx8[FLAT];
__device__ __align__(16) float g_top_w[FLAT];
__device__ __align__(16) float g_psum[N_EXP];

__device__ __forceinline__ unsigned f2tf(float f) {
    unsigned r;
    asm("cvt.rna.tf32.f32 %0, %1;" : "=r"(r) : "f"(f));
    return r;
}
#define MMA_TF32(c0, c1, c2, c3, a0, a1, a2, a3, b0, b1)                      \
    asm volatile(                                                             \
        "mma.sync.aligned.m16n8k8.row.col.f32.tf32.tf32.f32 "                 \
        "{%0,%1,%2,%3}, {%4,%5,%6,%7}, {%8,%9}, {%0,%1,%2,%3};"               \
        : "+f"(c0), "+f"(c1), "+f"(c2), "+f"(c3)                              \
        : "r"(a0), "r"(a1), "r"(a2), "r"(a3), "r"(b0), "r"(b1))

// ---------------- zero-fill + scratch init --------------------------------
__global__ void __launch_bounds__(256)
k_zero(float4* __restrict__ zb, float* __restrict__ out_loss) {
    size_t i = (size_t)blockIdx.x * 256 + threadIdx.x;
    const float4 z = make_float4(0.f, 0.f, 0.f, 0.f);
#pragma unroll
    for (int j = 0; j < 80; j++) zb[i + (size_t)j * 524288] = z;
    if (blockIdx.x == 0) {
        if (threadIdx.x < N_EXP) g_psum[threadIdx.x] = 0.0f;
        if (threadIdx.x == 64) out_loss[0] = 0.0f;
    }
}

// ---------------- gate transpose ------------------------------------------
__global__ void k_transpose_gate(const float* __restrict__ gate_w) {
    int idx = blockIdx.x * blockDim.x + threadIdx.x;   // covers D*E
    int k = idx >> 6;
    int e = idx & 63;
    g_gate_t[idx] = gate_w[(size_t)e * D_DIM + k];
}

// ---------------- 3xTF32 mma.sync GEMM + softmax + top2 -------------------
__global__ void __launch_bounds__(256)
k_gemm(const float* __restrict__ x, float* __restrict__ probs_out) {
    extern __shared__ unsigned sm[];
    __shared__ float smax[64], sinv[64];

    const int tid  = threadIdx.x;
    const int wid  = tid >> 5;
    const int lane = tid & 31;
    const int n0   = blockIdx.x * 64;

    // warp tile: 16 tokens x 32 experts
    const int wm = (wid & 3) * 16;       // token offset within block tile
    const int wn = (wid >> 2) * 32;      // expert offset

    float c[4][4];
#pragma unroll
    for (int nt = 0; nt < 4; nt++)
#pragma unroll
        for (int j = 0; j < 4; j++) c[nt][j] = 0.0f;

    const int g = lane >> 2;             // 0..7
    const int t4 = lane & 3;             // 0..3
    // A fragment base: row = wm + g, col = t4 (within k-tile)
    const unsigned abase = (unsigned)((wm + g) * LDS_S + t4);
    // B fragment base: row(k) = t4, col = wn + g
    const unsigned bbase = (unsigned)(t4 * LDS_S + wn + g);

    for (int kc = 0; kc < D_DIM; kc += TILE_K) {
        // ---- load + split x tile (64 tok x 64 k) and gate tile (64k x 64e)
#pragma unroll
        for (int l = 0; l < 4; l++) {
            int idx = tid + l * 256;
            int r = idx >> 4, q = (idx & 15) * 4;
            float4 v = *(const float4*)&x[(size_t)(n0 + r) * D_DIM + kc + q];
            unsigned b0 = f2tf(v.x), b1 = f2tf(v.y),
                     b2 = f2tf(v.z), b3 = f2tf(v.w);
            unsigned s0 = f2tf(v.x - __uint_as_float(b0));
            unsigned s1 = f2tf(v.y - __uint_as_float(b1));
            unsigned s2 = f2tf(v.z - __uint_as_float(b2));
            unsigned s3 = f2tf(v.w - __uint_as_float(b3));
            *(uint4*)&sm[XB_OFF + r * LDS_S + q] = make_uint4(b0, b1, b2, b3);
            *(uint4*)&sm[XS_OFF + r * LDS_S + q] = make_uint4(s0, s1, s2, s3);

            float4 w = *(const float4*)&g_gate_t[(size_t)(kc + r) * N_EXP + q];
            unsigned gb0 = f2tf(w.x), gb1 = f2tf(w.y),
                     gb2 = f2tf(w.z), gb3 = f2tf(w.w);
            unsigned gs0 = f2tf(w.x - __uint_as_float(gb0));
            unsigned gs1 = f2tf(w.y - __uint_as_float(gb1));
            unsigned gs2 = f2tf(w.z - __uint_as_float(gb2));
            unsigned gs3 = f2tf(w.w - __uint_as_float(gb3));
            *(uint4*)&sm[GB_OFF + r * LDS_S + q] = make_uint4(gb0, gb1, gb2, gb3);
            *(uint4*)&sm[GS_OFF + r * LDS_S + q] = make_uint4(gs0, gs1, gs2, gs3);
        }
        __syncthreads();

#pragma unroll
        for (int ks = 0; ks < 8; ks++) {
            const unsigned ao = abase + ks * 8;
            const unsigned bo = bbase + ks * 8 * LDS_S;
            // A fragments (big + small)
            unsigned ab0 = sm[XB_OFF + ao];
            unsigned ab1 = sm[XB_OFF + ao + 8 * LDS_S];
            unsigned ab2 = sm[XB_OFF + ao + 4];
            unsigned ab3 = sm[XB_OFF + ao + 8 * LDS_S + 4];
            unsigned as0 = sm[XS_OFF + ao];
            unsigned as1 = sm[XS_OFF + ao + 8 * LDS_S];
            unsigned as2 = sm[XS_OFF + ao + 4];
            unsigned as3 = sm[XS_OFF + ao + 8 * LDS_S + 4];
#pragma unroll
            for (int nt = 0; nt < 4; nt++) {
                unsigned bn = bo + nt * 8;
                unsigned bb0 = sm[GB_OFF + bn];
                unsigned bb1 = sm[GB_OFF + bn + 4 * LDS_S];
                unsigned bs0 = sm[GS_OFF + bn];
                unsigned bs1 = sm[GS_OFF + bn + 4 * LDS_S];
                MMA_TF32(c[nt][0], c[nt][1], c[nt][2], c[nt][3],
                         ab0, ab1, ab2, ab3, bb0, bb1);
                MMA_TF32(c[nt][0], c[nt][1], c[nt][2], c[nt][3],
                         ab0, ab1, ab2, ab3, bs0, bs1);
                MMA_TF32(c[nt][0], c[nt][1], c[nt][2], c[nt][3],
                         as0, as1, as2, as3, bb0, bb1);
            }
        }
        __syncthreads();
    }

    // ---- stage logits into smem (reuse XB region), [64][68] --------------
    float* lg = (float*)sm;
    {
        const int r0 = wm + g;
#pragma unroll
        for (int nt = 0; nt < 4; nt++) {
            int col = wn + nt * 8 + 2 * t4;
            lg[r0 * LDS_S + col]           = c[nt][0];
            lg[r0 * LDS_S + col + 1]       = c[nt][1];
            lg[(r0 + 8) * LDS_S + col]     = c[nt][2];
            lg[(r0 + 8) * LDS_S + col + 1] = c[nt][3];
        }
    }
    __syncthreads();

    // ---- per-token softmax stats + exact top-2 ---------------------------
    if (tid < 64) {
        const int t = tid;
        float m = -INFINITY;
#pragma unroll
        for (int e = 0; e < N_EXP; e++) m = fmaxf(m, lg[t * LDS_S + e]);
        float s = 0.0f;
#pragma unroll
        for (int e = 0; e < N_EXP; e++) s += expf(lg[t * LDS_S + e] - m);
        float inv = 1.0f / s;
        smax[t] = m;
        sinv[t] = inv;

        float v1 = -INFINITY, v2 = -INFINITY;
        int i1 = 0, i2 = 0;
#pragma unroll
        for (int e = 0; e < N_EXP; e++) {
            float v = lg[t * LDS_S + e];
            if (v > v1) { v2 = v1; i2 = i1; v1 = v; i1 = e; }
            else if (v > v2) { v2 = v; i2 = e; }
        }
        float p1 = expf(v1 - m) * inv;
        float p2 = expf(v2 - m) * inv;
        float r = 1.0f / (p1 + p2);
        int n = n0 + t;
        g_top_idx8[2 * n]     = (unsigned char)i1;
        g_top_idx8[2 * n + 1] = (unsigned char)i2;
        g_top_w[2 * n]     = p1 * r;
        g_top_w[2 * n + 1] = p2 * r;
    }
    __syncthreads();

    // ---- probs: 1 token x 16 experts per thread; keep p in lg ------------
    {
        int t = tid >> 2;
        int e0 = (tid & 3) * 16;
        float m = smax[t], inv = sinv[t];
        float buf[16];
#pragma unroll
        for (int i = 0; i < 16; i++)
            buf[i] = expf(lg[t * LDS_S + e0 + i] - m) * inv;
        float4* dst = (float4*)&probs_out[(size_t)(n0 + t) * N_EXP + e0];
#pragma unroll
        for (int q = 0; q < 4; q++)
            dst[q] = make_float4(buf[4 * q], buf[4 * q + 1],
                                 buf[4 * q + 2], buf[4 * q + 3]);
#pragma unroll
        for (int i = 0; i < 16; i++) lg[t * LDS_S + e0 + i] = buf[i];
    }
    __syncthreads();

    if (tid < 64) {
        const int e = tid;
        float s = 0.0f;
#pragma unroll
        for (int t = 0; t < 64; t++) s += lg[t * LDS_S + e];
        atomicAdd(&g_psum[e], s);
    }
}

// ---------------- scan + scatter + loss (one block per expert) ------------
__global__ void __launch_bounds__(256)
k_scan_scatter_loss(float* __restrict__ out_mask,
                    float* __restrict__ out_comb,
                    float* __restrict__ out_loss) {
    __shared__ int warp_sums[8];
    const int e = blockIdx.x;
    const int tid = threadIdx.x;
    const int lane = tid & 31;
    const int wid = tid >> 5;

    uint4 wv[4];
#pragma unroll
    for (int i = 0; i < 4; i++)
        wv[i] = ((const uint4*)g_top_idx8)[tid * 4 + i];
    unsigned w[16];
#pragma unroll
    for (int i = 0; i < 4; i++) {
        w[4 * i + 0] = wv[i].x; w[4 * i + 1] = wv[i].y;
        w[4 * i + 2] = wv[i].z; w[4 * i + 3] = wv[i].w;
    }

    const unsigned eb = (unsigned)e * 0x01010101u;
    int local = 0;
#pragma unroll
    for (int i = 0; i < 16; i++) local += __popc(__vcmpeq4(w[i], eb));
    local >>= 3;

    int incl = local;
#pragma unroll
    for (int off = 1; off < 32; off <<= 1) {
        int v = __shfl_up_sync(0xffffffffu, incl, off);
        if (lane >= off) incl += v;
    }
    if (lane == 31) warp_sums[wid] = incl;
    __syncthreads();
    int base = 0;
#pragma unroll
    for (int j = 0; j < 8; j++) base += (j < wid) ? warp_sums[j] : 0;

    int c = base + incl - local;   // exclusive prefix for this thread
#pragma unroll
    for (int i = 0; i < 16; i++) {
        unsigned word = w[i];
#pragma unroll
        for (int b = 0; b < 4; b++) {
            if (((word >> (8 * b)) & 0xffu) == (unsigned)e) {
                if (c < CAP) {
                    int fi = tid * 64 + i * 4 + b;
                    size_t off = (size_t)(fi >> 1) * (N_EXP * CAP)
                               + (size_t)e * CAP + c;
                    out_mask[off] = 1.0f;
                    out_comb[off] = g_top_w[fi];
                }
                c++;
            }
        }
    }
    if (tid == 255) {
        int total = base + incl;
        float f = (float)total / (float)FLAT;
        float p = g_psum[e] / (float)N_TOK;
        atomicAdd(out_loss, 0.01f * (float)N_EXP * f * p);
    }
}

// ---------------- launch ---------------------------------------------------
extern "C" void kernel_launch(void* const* d_in, const int* in_sizes, int n_in,
                              void* d_out, int out_size) {
    const float* x      = (const float*)d_in[0];
    const float* gate_w = (const float*)d_in[1];
    float* out = (float*)d_out;

    float* out_mask  = out;                                   // N*E*C
    float* out_comb  = out + (size_t)NEC;                     // N*E*C
    float* out_probs = out + (size_t)2 * NEC;                 // N*E
    float* out_loss  = out + (size_t)2 * NEC + (size_t)N_TOK * N_EXP;

    cudaFuncSetAttribute(k_gemm,
        cudaFuncAttributeMaxDynamicSharedMemorySize, SMEM_BYTES);

    k_zero<<<2048, 256>>>((float4*)out, out_loss);
    k_transpose_gate<<<(D_DIM * N_EXP) / 256, 256>>>(gate_w);
    k_gemm<<<GEMM_GRID, 256, SMEM_BYTES>>>(x, out_probs);
    k_scan_scatter_loss<<<N_EXP, 256>>>(out_mask, out_comb, out_loss);
}